// round 14
// baseline (speedup 1.0000x reference)
#include <cuda_runtime.h>
#include <cuda_fp16.h>
#include <math.h>
#include <stdint.h>

// ---------------- problem constants ----------------
static constexpr int NUSERS = 100000;
static constexpr int NITEMS = 50000;
static constexpr int NNODE  = 150000;       // NUSERS + NITEMS
static constexpr int NEDGE  = 1200000;      // 2 * 600000
static constexpr int DIM    = 64;
static constexpr int SCANB  = (NNODE + 1023) / 1024;     // 147 scan blocks
static constexpr int EDGE4B = (NEDGE / 4 + 255) / 256;   // mlp blocks (4 edges/thread)
static constexpr int EDGE2B = (NEDGE / 2 + 255) / 256;   // scatter blocks
static constexpr int VECB   = (NNODE * 16 + 255) / 256;  // init blocks
static constexpr int GB     = (NNODE / 4 + 7) / 8;       // gather blocks (4 nodes/warp, 8 warps)

// ---------------- device scratch (static; no runtime alloc) ----------------
// Invariant: g_wdeg/g_cnt are ZERO at kernel_launch entry (static init covers
// the first call; gather layer 0 re-zeros them after scan3 has consumed them).
__device__ float  g_edge_w[NEDGE];
__device__ int    g_rank[NEDGE];            // rank of edge within its dst bucket
__device__ int2   g_edge[NEDGE];            // {src, __float_as_int(edge_w * dinv[src])}
__device__ float  g_wdeg[NNODE];
__device__ float  g_dinv[NNODE];
__device__ int    g_cnt[NNODE];
__device__ int    g_rowptr[NNODE + 1];
__device__ int    g_bsum[SCANB];
__device__ __half g_x0[(size_t)NNODE * DIM];
__device__ __half g_x1[(size_t)NNODE * DIM];
__device__ __half g_x2[(size_t)NNODE * DIM];
__device__ __half* const g_xptr[3] = {g_x0, g_x1, g_x2};

// ---------------- fused mlp (4 edges/thread) + node init ----------------
// blocks [0, EDGE4B): edge MLP + wdeg/cnt histogram (rank captured)
// blocks [EDGE4B, EDGE4B+VECB): x0 = l2norm(...) node init (independent)
__global__ void __launch_bounds__(256) mlpinit_kernel(
        const float* __restrict__ ef,
        const float* __restrict__ w1,    const float* __restrict__ b1,
        const float* __restrict__ w2,    const float* __restrict__ b2,
        const int*   __restrict__ eidx,
        const float* __restrict__ uemb,  const float* __restrict__ audio,
        const float* __restrict__ art,   const float* __restrict__ alb,
        const int*   __restrict__ aid,   const int*   __restrict__ bid) {
    int t = threadIdx.x;
    if (blockIdx.x < EDGE4B) {
        __shared__ float sW1[8 * 32];
        __shared__ float sB1[32];
        __shared__ float sW2[32];
        __shared__ float sB2;
        if (t < 256) sW1[t] = w1[t];
        if (t < 32)  { sB1[t] = b1[t]; sW2[t] = w2[t]; }
        if (t == 0)  sB2 = b2[0];
        __syncthreads();

        int e0 = (blockIdx.x * 256 + t) * 4;
        if (e0 >= NEDGE) return;           // NEDGE % 4 == 0: all 4 edges valid

        float f[4][8];
        #pragma unroll
        for (int c = 0; c < 4; c++) {
            const float4* fp = reinterpret_cast<const float4*>(ef + (size_t)(e0 + c) * 8);
            float4 fa = __ldg(fp);
            float4 fb = __ldg(fp + 1);
            f[c][0] = fa.x; f[c][1] = fa.y; f[c][2] = fa.z; f[c][3] = fa.w;
            f[c][4] = fb.x; f[c][5] = fb.y; f[c][6] = fb.z; f[c][7] = fb.w;
        }
        float out[4] = {sB2, sB2, sB2, sB2};
        #pragma unroll
        for (int j = 0; j < 32; j++) {
            float wc[8];
            #pragma unroll
            for (int i = 0; i < 8; i++) wc[i] = sW1[i * 32 + j];   // 8 LDS serve 32 FMAs
            float bj = sB1[j], w2j = sW2[j];
            #pragma unroll
            for (int c = 0; c < 4; c++) {
                float h = bj;
                #pragma unroll
                for (int i = 0; i < 8; i++) h = fmaf(f[c][i], wc[i], h);
                h = fmaxf(h, 0.f);
                out[c] = fmaf(h, w2j, out[c]);
            }
        }
        int4 c4 = __ldg(reinterpret_cast<const int4*>(eidx + NEDGE + e0));
        int cs[4] = {c4.x, c4.y, c4.z, c4.w};
        float wv[4];
        #pragma unroll
        for (int c = 0; c < 4; c++) wv[c] = 1.f / (1.f + expf(-out[c]));
        *reinterpret_cast<float4*>(g_edge_w + e0) = make_float4(wv[0], wv[1], wv[2], wv[3]);
        int rk[4];
        #pragma unroll
        for (int c = 0; c < 4; c++) {
            atomicAdd(&g_wdeg[cs[c]], wv[c]);
            rk[c] = atomicAdd(&g_cnt[cs[c]], 1);
        }
        *reinterpret_cast<int4*>(g_rank + e0) = make_int4(rk[0], rk[1], rk[2], rk[3]);
    } else {
        int g = (blockIdx.x - EDGE4B) * 256 + t;
        int node = g >> 4;
        int sub  = g & 15;
        if (node >= NNODE) return;

        float4 v;
        if (node < NUSERS) {
            v = __ldg(reinterpret_cast<const float4*>(uemb) + (size_t)node * 16 + sub);
        } else {
            int i = node - NUSERS;
            int a = __ldg(&aid[i]);
            int b = __ldg(&bid[i]);
            float4 pa = __ldg(reinterpret_cast<const float4*>(audio) + (size_t)i * 16 + sub);
            float4 pr = __ldg(reinterpret_cast<const float4*>(art)   + (size_t)a * 16 + sub);
            float4 pl = __ldg(reinterpret_cast<const float4*>(alb)   + (size_t)b * 16 + sub);
            v.x = pa.x * 0.3f + (pr.x + pl.x) * 0.44f;
            v.y = pa.y * 0.3f + (pr.y + pl.y) * 0.44f;
            v.z = pa.z * 0.3f + (pr.z + pl.z) * 0.44f;
            v.w = pa.w * 0.3f + (pr.w + pl.w) * 0.44f;
        }
        float ss = v.x * v.x + v.y * v.y + v.z * v.z + v.w * v.w;
        #pragma unroll
        for (int o = 8; o > 0; o >>= 1) ss += __shfl_xor_sync(0xffffffffu, ss, o);
        float inv = 1.f / fmaxf(sqrtf(ss), 1e-12f);

        __half2 h0 = __floats2half2_rn(v.x * inv, v.y * inv);
        __half2 h1 = __floats2half2_rn(v.z * inv, v.w * inv);
        uint2 hv;
        hv.x = *reinterpret_cast<unsigned int*>(&h0);
        hv.y = *reinterpret_cast<unsigned int*>(&h1);
        reinterpret_cast<uint2*>(g_x0)[(size_t)node * 16 + sub] = hv;
    }
}

// scan phase 1: per-block sums of g_cnt
__global__ void __launch_bounds__(1024) scan1_kernel() {
    __shared__ int sh[1024];
    int n = blockIdx.x * 1024 + threadIdx.x;
    int s = (n < NNODE) ? g_cnt[n] : 0;
    sh[threadIdx.x] = s;
    __syncthreads();
    for (int off = 512; off > 0; off >>= 1) {
        if (threadIdx.x < off) sh[threadIdx.x] += sh[threadIdx.x + off];
        __syncthreads();
    }
    if (threadIdx.x == 0) g_bsum[blockIdx.x] = sh[0];
}

// scan phase 2+3: each block redundantly scans the 147 block sums, then does
// its local exclusive scan and writes rowptr/dinv.
__global__ void __launch_bounds__(1024) scan3_kernel() {
    __shared__ int sums[256];
    __shared__ int sh[1024];
    int t = threadIdx.x;
    if (t < 256) sums[t] = (t < SCANB) ? g_bsum[t] : 0;
    __syncthreads();
    for (int off = 1; off < 256; off <<= 1) {
        int v = (t < 256 && t >= off) ? sums[t - off] : 0;
        __syncthreads();
        if (t < 256) sums[t] += v;
        __syncthreads();
    }
    int blockOff = (blockIdx.x == 0) ? 0 : sums[blockIdx.x - 1];

    int n = blockIdx.x * 1024 + t;
    int c = (n < NNODE) ? g_cnt[n] : 0;
    sh[t] = c;
    __syncthreads();
    for (int off = 1; off < 1024; off <<= 1) {
        int v = (t >= off) ? sh[t - off] : 0;
        __syncthreads();
        sh[t] += v;
        __syncthreads();
    }
    if (n < NNODE) {
        g_rowptr[n] = blockOff + sh[t] - c;
        float dg = g_wdeg[n];
        g_dinv[n] = (dg > 0.f) ? rsqrtf(dg) : 0.f;
    }
    if (blockIdx.x == 0 && t == 0) g_rowptr[NNODE] = NEDGE;
}

// ATOMIC-FREE scatter: position = rowptr[dst] + rank; 2 edges/thread
__global__ void __launch_bounds__(256) scatter_kernel(const int* __restrict__ eidx) {
    int e = (blockIdx.x * 256 + threadIdx.x) * 2;
    if (e >= NEDGE) return;
    int2   r2 = __ldg(reinterpret_cast<const int2*>(eidx + e));
    int2   c2 = __ldg(reinterpret_cast<const int2*>(eidx + NEDGE + e));
    float2 w2 = __ldg(reinterpret_cast<const float2*>(g_edge_w + e));
    int2   k2 = __ldg(reinterpret_cast<const int2*>(g_rank + e));

    float wa = w2.x * __ldg(&g_dinv[r2.x]);
    g_edge[__ldg(&g_rowptr[c2.x]) + k2.x] = make_int2(r2.x, __float_as_int(wa));

    float wb = w2.y * __ldg(&g_dinv[r2.y]);
    g_edge[__ldg(&g_rowptr[c2.y]) + k2.y] = make_int2(r2.y, __float_as_int(wb));
}

// ---- gather segment: lane owns dims {2*lane, 2*lane+1} of the dst node ----
__device__ __forceinline__ float2 gather_seg(const unsigned* __restrict__ xin,
                                             int beg, int end, int lane) {
    float a0 = 0.f, a1 = 0.f;
    for (int base = beg; base < end; base += 32) {
        int idx = base + lane;
        int2 m = (idx < end) ? __ldg(&g_edge[idx]) : make_int2(0, 0);
        int nr = (min(end - base, 32) + 7) & ~7;   // round up to group of 8
        for (int g = 0; g < nr; g += 8) {
            unsigned v[8];
            float    w[8];
            #pragma unroll
            for (int k = 0; k < 8; k++) {
                int src = __shfl_sync(0xffffffffu, m.x, g + k);
                w[k] = __int_as_float(__shfl_sync(0xffffffffu, m.y, g + k));
                v[k] = __ldg(xin + (size_t)src * 32 + lane);
            }
            #pragma unroll
            for (int k = 0; k < 8; k++) {
                float2 f = __half22float2(*reinterpret_cast<__half2*>(&v[k]));
                a0 = fmaf(w[k], f.x, a0);
                a1 = fmaf(w[k], f.y, a1);
            }
        }
    }
    return make_float2(a0, a1);
}

// layers 0,1: x[l+1][n] = dinv[n] * sum.  Warp = 4 consecutive nodes (adjacent
// CSR segments, shared prologue). Layer 0 also re-zeros wdeg/cnt (post-scan).
__global__ void __launch_bounds__(256) gather_kernel(int layer) {
    const unsigned* __restrict__ xin  = reinterpret_cast<const unsigned*>(g_xptr[layer]);
    unsigned*       __restrict__ xout = reinterpret_cast<unsigned*>(g_xptr[layer + 1]);

    int gt = blockIdx.x * blockDim.x + threadIdx.x;
    if (layer == 0 && gt < NNODE) { g_wdeg[gt] = 0.f; g_cnt[gt] = 0; }

    int lane = threadIdx.x & 31;
    int n0 = (gt >> 5) * 4;                        // 4 nodes per warp
    if (n0 >= NNODE) return;

    int rp = __ldg(&g_rowptr[n0 + min(lane, 4)]);
    float dvl = __ldg(&g_dinv[n0 + (lane & 3)]);
    #pragma unroll
    for (int c = 0; c < 4; c++) {
        int beg = __shfl_sync(0xffffffffu, rp, c);
        int end = __shfl_sync(0xffffffffu, rp, c + 1);
        float dv = __shfl_sync(0xffffffffu, dvl, c);
        float2 a = gather_seg(xin, beg, end, lane);
        __half2 h = __floats2half2_rn(a.x * dv, a.y * dv);
        xout[(size_t)(n0 + c) * 32 + lane] = *reinterpret_cast<unsigned*>(&h);
    }
}

// layer 2 fused with final: out = l2norm((x0+x1+x2+x3)/4), x3 kept fp32.
__global__ void __launch_bounds__(256) gatherfinal_kernel(float* __restrict__ out) {
    int gt = blockIdx.x * blockDim.x + threadIdx.x;
    if (gt == 0) out[(size_t)NNODE * DIM] = 0.f;   // align_loss scalar

    int lane = threadIdx.x & 31;
    int n0 = (gt >> 5) * 4;
    if (n0 >= NNODE) return;

    int rp = __ldg(&g_rowptr[n0 + min(lane, 4)]);
    float dvl = __ldg(&g_dinv[n0 + (lane & 3)]);
    const unsigned* x2p = reinterpret_cast<const unsigned*>(g_x2);
    float2* op = reinterpret_cast<float2*>(out);

    #pragma unroll
    for (int c = 0; c < 4; c++) {
        int beg = __shfl_sync(0xffffffffu, rp, c);
        int end = __shfl_sync(0xffffffffu, rp, c + 1);
        float dv = __shfl_sync(0xffffffffu, dvl, c);
        int node = n0 + c;

        float2 a = gather_seg(x2p, beg, end, lane);
        float s0 = a.x * dv, s1 = a.y * dv;        // x3 in fp32 (pre-rounding)
        #pragma unroll
        for (int l = 0; l < 3; l++) {
            unsigned v = __ldg(reinterpret_cast<const unsigned*>(g_xptr[l]) + (size_t)node * 32 + lane);
            float2 f = __half22float2(*reinterpret_cast<__half2*>(&v));
            s0 += f.x;
            s1 += f.y;
        }
        s0 *= 0.25f;
        s1 *= 0.25f;
        float ss = fmaf(s0, s0, s1 * s1);
        #pragma unroll
        for (int o = 16; o > 0; o >>= 1) ss += __shfl_xor_sync(0xffffffffu, ss, o);
        float inv = 1.f / fmaxf(sqrtf(ss), 1e-12f);
        op[(size_t)node * 32 + lane] = make_float2(s0 * inv, s1 * inv);
    }
}

// ---------------- launcher ----------------
extern "C" void kernel_launch(void* const* d_in, const int* in_sizes, int n_in,
                              void* d_out, int out_size) {
    const float* uemb  = (const float*)d_in[0];
    const float* audio = (const float*)d_in[1];
    const float* art   = (const float*)d_in[2];
    const float* alb   = (const float*)d_in[3];
    const float* w1    = (const float*)d_in[4];
    const float* b1    = (const float*)d_in[5];
    const float* w2    = (const float*)d_in[6];
    const float* b2    = (const float*)d_in[7];
    const float* ef    = (const float*)d_in[8];
    const int*   eidx  = (const int*)  d_in[9];
    const int*   aid   = (const int*)  d_in[10];
    const int*   bid   = (const int*)  d_in[11];
    float* out = (float*)d_out;

    mlpinit_kernel    <<<EDGE4B + VECB, 256>>>(ef, w1, b1, w2, b2, eidx,
                                               uemb, audio, art, alb, aid, bid);
    scan1_kernel      <<<SCANB, 1024>>>();
    scan3_kernel      <<<SCANB, 1024>>>();
    scatter_kernel    <<<EDGE2B, 256>>>(eidx);
    gather_kernel     <<<GB, 256>>>(0);   // x0 -> x1  (also re-zeros wdeg/cnt)
    gather_kernel     <<<GB, 256>>>(1);   // x1 -> x2
    gatherfinal_kernel<<<GB, 256>>>(out); // x2 -> out (fused final)
}

// round 15
// speedup vs baseline: 1.0859x; 1.0859x over previous
#include <cuda_runtime.h>
#include <cuda_fp16.h>
#include <math.h>
#include <stdint.h>

// ---------------- problem constants ----------------
static constexpr int NUSERS = 100000;
static constexpr int NITEMS = 50000;
static constexpr int NNODE  = 150000;       // NUSERS + NITEMS
static constexpr int NEDGE  = 1200000;      // 2 * 600000
static constexpr int DIM    = 64;
static constexpr int SCANB  = (NNODE + 1023) / 1024;     // 147 scan blocks
static constexpr int EDGE4B = (NEDGE / 4 + 255) / 256;   // mlp blocks (4 edges/thread)
static constexpr int EDGE2B = (NEDGE / 2 + 255) / 256;   // scatter blocks
static constexpr int VECB   = (NNODE * 16 + 255) / 256;  // init blocks
static constexpr int GB     = NNODE / 16;                // gather blocks (2 nodes/warp, 8 warps)

// ---------------- device scratch (static; no runtime alloc) ----------------
// Invariant: g_wdeg/g_cnt are ZERO at kernel_launch entry (static init covers
// the first call; gather layer 0 re-zeros them after scan3 has consumed them).
__device__ float  g_edge_w[NEDGE];
__device__ int    g_rank[NEDGE];            // rank of edge within its dst bucket
__device__ int2   g_edge[NEDGE];            // {src, __float_as_int(edge_w * dinv[src])}
__device__ float  g_wdeg[NNODE];
__device__ float  g_dinv[NNODE];
__device__ int    g_cnt[NNODE];
__device__ int    g_rowptr[NNODE + 1];
__device__ int    g_bsum[SCANB];
__device__ __half g_x0[(size_t)NNODE * DIM];
__device__ __half g_x1[(size_t)NNODE * DIM];
__device__ __half g_x2[(size_t)NNODE * DIM];
__device__ __half* const g_xptr[3] = {g_x0, g_x1, g_x2};

// ---------------- kernels ----------------

// edge gate MLP, 4 edges per thread: sigmoid(relu(f @ W1 + b1) @ w2 + b2).
// Each set of 8 weight LDS feeds 32 FMAs (vs 8 in the 1-edge version).
// Histogram wdeg + cnt; cnt atomic's return value = edge rank in dst bucket.
__global__ void __launch_bounds__(256) mlp_kernel(
        const float* __restrict__ ef,
        const float* __restrict__ w1,  const float* __restrict__ b1,
        const float* __restrict__ w2,  const float* __restrict__ b2,
        const int*   __restrict__ eidx) {
    __shared__ float sW1[8 * 32];
    __shared__ float sB1[32];
    __shared__ float sW2[32];
    __shared__ float sB2;
    int t = threadIdx.x;
    if (t < 256) sW1[t] = w1[t];
    if (t < 32)  { sB1[t] = b1[t]; sW2[t] = w2[t]; }
    if (t == 0)  sB2 = b2[0];
    __syncthreads();

    int e0 = (blockIdx.x * 256 + t) * 4;
    if (e0 >= NEDGE) return;               // NEDGE % 4 == 0: all 4 edges valid

    float f[4][8];
    #pragma unroll
    for (int c = 0; c < 4; c++) {
        const float4* fp = reinterpret_cast<const float4*>(ef + (size_t)(e0 + c) * 8);
        float4 fa = __ldg(fp);
        float4 fb = __ldg(fp + 1);
        f[c][0] = fa.x; f[c][1] = fa.y; f[c][2] = fa.z; f[c][3] = fa.w;
        f[c][4] = fb.x; f[c][5] = fb.y; f[c][6] = fb.z; f[c][7] = fb.w;
    }
    float out[4] = {sB2, sB2, sB2, sB2};
    #pragma unroll
    for (int j = 0; j < 32; j++) {
        float wc[8];
        #pragma unroll
        for (int i = 0; i < 8; i++) wc[i] = sW1[i * 32 + j];   // 8 LDS serve 32 FMAs
        float bj = sB1[j], w2j = sW2[j];
        #pragma unroll
        for (int c = 0; c < 4; c++) {
            float h = bj;
            #pragma unroll
            for (int i = 0; i < 8; i++) h = fmaf(f[c][i], wc[i], h);
            h = fmaxf(h, 0.f);
            out[c] = fmaf(h, w2j, out[c]);
        }
    }
    int4 c4 = __ldg(reinterpret_cast<const int4*>(eidx + NEDGE + e0));
    int cs[4] = {c4.x, c4.y, c4.z, c4.w};
    float wv[4];
    #pragma unroll
    for (int c = 0; c < 4; c++) wv[c] = 1.f / (1.f + expf(-out[c]));
    *reinterpret_cast<float4*>(g_edge_w + e0) = make_float4(wv[0], wv[1], wv[2], wv[3]);
    int rk[4];
    #pragma unroll
    for (int c = 0; c < 4; c++) {
        atomicAdd(&g_wdeg[cs[c]], wv[c]);
        rk[c] = atomicAdd(&g_cnt[cs[c]], 1);
    }
    *reinterpret_cast<int4*>(g_rank + e0) = make_int4(rk[0], rk[1], rk[2], rk[3]);
}

// scan phase 1: per-block sums of g_cnt
__global__ void __launch_bounds__(1024) scan1_kernel() {
    __shared__ int sh[1024];
    int n = blockIdx.x * 1024 + threadIdx.x;
    int s = (n < NNODE) ? g_cnt[n] : 0;
    sh[threadIdx.x] = s;
    __syncthreads();
    for (int off = 512; off > 0; off >>= 1) {
        if (threadIdx.x < off) sh[threadIdx.x] += sh[threadIdx.x + off];
        __syncthreads();
    }
    if (threadIdx.x == 0) g_bsum[blockIdx.x] = sh[0];
}

// scan phase 2+3: each block redundantly scans the 147 block sums, then does
// its local exclusive scan and writes rowptr/dinv.
__global__ void __launch_bounds__(1024) scan3_kernel() {
    __shared__ int sums[256];
    __shared__ int sh[1024];
    int t = threadIdx.x;
    if (t < 256) sums[t] = (t < SCANB) ? g_bsum[t] : 0;
    __syncthreads();
    for (int off = 1; off < 256; off <<= 1) {
        int v = (t < 256 && t >= off) ? sums[t - off] : 0;
        __syncthreads();
        if (t < 256) sums[t] += v;
        __syncthreads();
    }
    int blockOff = (blockIdx.x == 0) ? 0 : sums[blockIdx.x - 1];

    int n = blockIdx.x * 1024 + t;
    int c = (n < NNODE) ? g_cnt[n] : 0;
    sh[t] = c;
    __syncthreads();
    for (int off = 1; off < 1024; off <<= 1) {
        int v = (t >= off) ? sh[t - off] : 0;
        __syncthreads();
        sh[t] += v;
        __syncthreads();
    }
    if (n < NNODE) {
        g_rowptr[n] = blockOff + sh[t] - c;
        float dg = g_wdeg[n];
        g_dinv[n] = (dg > 0.f) ? rsqrtf(dg) : 0.f;
    }
    if (blockIdx.x == 0 && t == 0) g_rowptr[NNODE] = NEDGE;
}

// fused scatter + init (ATOMIC-FREE scatter: position = rowptr[dst] + rank):
//   blocks [0, EDGE2B): place edges {src, edge_w*dinv[src]} at their slot
//   blocks [EDGE2B, EDGE2B+VECB): x0 = l2norm(...) node init
__global__ void __launch_bounds__(256) scatterinit_kernel(
        const int*   __restrict__ eidx,
        const float* __restrict__ uemb,  const float* __restrict__ audio,
        const float* __restrict__ art,   const float* __restrict__ alb,
        const int*   __restrict__ aid,   const int*   __restrict__ bid) {
    if (blockIdx.x < EDGE2B) {
        int e = (blockIdx.x * 256 + threadIdx.x) * 2;
        if (e >= NEDGE) return;
        int2   r2 = __ldg(reinterpret_cast<const int2*>(eidx + e));
        int2   c2 = __ldg(reinterpret_cast<const int2*>(eidx + NEDGE + e));
        float2 w2 = __ldg(reinterpret_cast<const float2*>(g_edge_w + e));
        int2   k2 = __ldg(reinterpret_cast<const int2*>(g_rank + e));

        float wa = w2.x * __ldg(&g_dinv[r2.x]);
        g_edge[__ldg(&g_rowptr[c2.x]) + k2.x] = make_int2(r2.x, __float_as_int(wa));

        float wb = w2.y * __ldg(&g_dinv[r2.y]);
        g_edge[__ldg(&g_rowptr[c2.y]) + k2.y] = make_int2(r2.y, __float_as_int(wb));
    } else {
        int t = (blockIdx.x - EDGE2B) * 256 + threadIdx.x;
        int node = t >> 4;
        int sub  = t & 15;
        if (node >= NNODE) return;

        float4 v;
        if (node < NUSERS) {
            v = __ldg(reinterpret_cast<const float4*>(uemb) + (size_t)node * 16 + sub);
        } else {
            int i = node - NUSERS;
            int a = __ldg(&aid[i]);
            int b = __ldg(&bid[i]);
            float4 pa = __ldg(reinterpret_cast<const float4*>(audio) + (size_t)i * 16 + sub);
            float4 pr = __ldg(reinterpret_cast<const float4*>(art)   + (size_t)a * 16 + sub);
            float4 pl = __ldg(reinterpret_cast<const float4*>(alb)   + (size_t)b * 16 + sub);
            v.x = pa.x * 0.3f + (pr.x + pl.x) * 0.44f;
            v.y = pa.y * 0.3f + (pr.y + pl.y) * 0.44f;
            v.z = pa.z * 0.3f + (pr.z + pl.z) * 0.44f;
            v.w = pa.w * 0.3f + (pr.w + pl.w) * 0.44f;
        }
        float ss = v.x * v.x + v.y * v.y + v.z * v.z + v.w * v.w;
        #pragma unroll
        for (int o = 8; o > 0; o >>= 1) ss += __shfl_xor_sync(0xffffffffu, ss, o);
        float inv = 1.f / fmaxf(sqrtf(ss), 1e-12f);

        __half2 h0 = __floats2half2_rn(v.x * inv, v.y * inv);
        __half2 h1 = __floats2half2_rn(v.z * inv, v.w * inv);
        uint2 hv;
        hv.x = *reinterpret_cast<unsigned int*>(&h0);
        hv.y = *reinterpret_cast<unsigned int*>(&h1);
        reinterpret_cast<uint2*>(g_x0)[(size_t)node * 16 + sub] = hv;
    }
}

// ---- gather segment: lane owns dims {2*lane, 2*lane+1} of the dst node ----
// Edge meta for up to 32 edges staged in ONE coalesced int2 load; each edge is
// ONE warp-wide 128B row load (4B/lane). 8 independent loads in flight per
// group; padded edges contribute w=0 (src=0 is a valid, safe row).
__device__ __forceinline__ float2 gather_seg(const unsigned* __restrict__ xin,
                                             int beg, int end, int lane) {
    float a0 = 0.f, a1 = 0.f;
    for (int base = beg; base < end; base += 32) {
        int idx = base + lane;
        int2 m = (idx < end) ? __ldg(&g_edge[idx]) : make_int2(0, 0);
        int nr = (min(end - base, 32) + 7) & ~7;   // round up to group of 8
        for (int g = 0; g < nr; g += 8) {
            unsigned v[8];
            float    w[8];
            #pragma unroll
            for (int k = 0; k < 8; k++) {
                int src = __shfl_sync(0xffffffffu, m.x, g + k);
                w[k] = __int_as_float(__shfl_sync(0xffffffffu, m.y, g + k));
                v[k] = __ldg(xin + (size_t)src * 32 + lane);
            }
            #pragma unroll
            for (int k = 0; k < 8; k++) {
                float2 f = __half22float2(*reinterpret_cast<__half2*>(&v[k]));
                a0 = fmaf(w[k], f.x, a0);
                a1 = fmaf(w[k], f.y, a1);
            }
        }
    }
    return make_float2(a0, a1);
}

// layers 0,1: x[l+1][n] = dinv[n] * sum.  Warp = 2 consecutive nodes (adjacent
// CSR segments); shared prologue. Layer 0 also re-zeros wdeg/cnt (post-scan).
__global__ void __launch_bounds__(256) gather_kernel(int layer) {
    const unsigned* __restrict__ xin  = reinterpret_cast<const unsigned*>(g_xptr[layer]);
    unsigned*       __restrict__ xout = reinterpret_cast<unsigned*>(g_xptr[layer + 1]);

    int gt = blockIdx.x * blockDim.x + threadIdx.x;
    if (layer == 0 && gt < NNODE) { g_wdeg[gt] = 0.f; g_cnt[gt] = 0; }

    int lane = threadIdx.x & 31;
    int n0 = (gt >> 5) * 2;                       // 2 nodes per warp

    int rp = __ldg(&g_rowptr[n0 + min(lane, 2)]);
    int beg = __shfl_sync(0xffffffffu, rp, 0);
    int mid = __shfl_sync(0xffffffffu, rp, 1);
    int end = __shfl_sync(0xffffffffu, rp, 2);
    float dvl = __ldg(&g_dinv[n0 + (lane & 1)]);
    float dv0 = __shfl_sync(0xffffffffu, dvl, 0);
    float dv1 = __shfl_sync(0xffffffffu, dvl, 1);

    float2 a = gather_seg(xin, beg, mid, lane);
    __half2 h0 = __floats2half2_rn(a.x * dv0, a.y * dv0);
    xout[(size_t)n0 * 32 + lane] = *reinterpret_cast<unsigned*>(&h0);

    float2 b = gather_seg(xin, mid, end, lane);
    __half2 h1 = __floats2half2_rn(b.x * dv1, b.y * dv1);
    xout[(size_t)(n0 + 1) * 32 + lane] = *reinterpret_cast<unsigned*>(&h1);
}

// layer 2 fused with final: out = l2norm((x0+x1+x2+x3)/4), x3 kept fp32.
__global__ void __launch_bounds__(256) gatherfinal_kernel(float* __restrict__ out) {
    int gt = blockIdx.x * blockDim.x + threadIdx.x;
    if (gt == 0) out[(size_t)NNODE * DIM] = 0.f;   // align_loss scalar

    int lane = threadIdx.x & 31;
    int n0 = (gt >> 5) * 2;

    int rp = __ldg(&g_rowptr[n0 + min(lane, 2)]);
    int beg = __shfl_sync(0xffffffffu, rp, 0);
    int mid = __shfl_sync(0xffffffffu, rp, 1);
    int end = __shfl_sync(0xffffffffu, rp, 2);
    float dvl = __ldg(&g_dinv[n0 + (lane & 1)]);
    float dv0 = __shfl_sync(0xffffffffu, dvl, 0);
    float dv1 = __shfl_sync(0xffffffffu, dvl, 1);

    const unsigned* x2p = reinterpret_cast<const unsigned*>(g_x2);
    float2 a = gather_seg(x2p, beg, mid, lane);
    float2 b = gather_seg(x2p, mid, end, lane);

    float s0 = a.x * dv0, s1 = a.y * dv0;   // node n0
    float t0 = b.x * dv1, t1 = b.y * dv1;   // node n0+1

    #pragma unroll
    for (int l = 0; l < 3; l++) {
        const unsigned* xp = reinterpret_cast<const unsigned*>(g_xptr[l]);
        unsigned va = __ldg(xp + (size_t)n0 * 32 + lane);
        unsigned vb = __ldg(xp + (size_t)(n0 + 1) * 32 + lane);
        float2 fa = __half22float2(*reinterpret_cast<__half2*>(&va));
        float2 fb = __half22float2(*reinterpret_cast<__half2*>(&vb));
        s0 += fa.x; s1 += fa.y;
        t0 += fb.x; t1 += fb.y;
    }
    s0 *= 0.25f; s1 *= 0.25f; t0 *= 0.25f; t1 *= 0.25f;
    float ssA = fmaf(s0, s0, s1 * s1);
    float ssB = fmaf(t0, t0, t1 * t1);
    #pragma unroll
    for (int o = 16; o > 0; o >>= 1) {
        ssA += __shfl_xor_sync(0xffffffffu, ssA, o);
        ssB += __shfl_xor_sync(0xffffffffu, ssB, o);
    }
    float invA = 1.f / fmaxf(sqrtf(ssA), 1e-12f);
    float invB = 1.f / fmaxf(sqrtf(ssB), 1e-12f);

    float2* op = reinterpret_cast<float2*>(out);
    op[(size_t)n0 * 32 + lane]       = make_float2(s0 * invA, s1 * invA);
    op[(size_t)(n0 + 1) * 32 + lane] = make_float2(t0 * invB, t1 * invB);
}

// ---------------- launcher ----------------
extern "C" void kernel_launch(void* const* d_in, const int* in_sizes, int n_in,
                              void* d_out, int out_size) {
    const float* uemb  = (const float*)d_in[0];
    const float* audio = (const float*)d_in[1];
    const float* art   = (const float*)d_in[2];
    const float* alb   = (const float*)d_in[3];
    const float* w1    = (const float*)d_in[4];
    const float* b1    = (const float*)d_in[5];
    const float* w2    = (const float*)d_in[6];
    const float* b2    = (const float*)d_in[7];
    const float* ef    = (const float*)d_in[8];
    const int*   eidx  = (const int*)  d_in[9];
    const int*   aid   = (const int*)  d_in[10];
    const int*   bid   = (const int*)  d_in[11];
    float* out = (float*)d_out;

    mlp_kernel        <<<EDGE4B, 256>>>(ef, w1, b1, w2, b2, eidx);
    scan1_kernel      <<<SCANB, 1024>>>();
    scan3_kernel      <<<SCANB, 1024>>>();
    scatterinit_kernel<<<EDGE2B + VECB, 256>>>(eidx, uemb, audio, art, alb, aid, bid);
    gather_kernel     <<<GB, 256>>>(0);   // x0 -> x1  (also re-zeros wdeg/cnt)
    gather_kernel     <<<GB, 256>>>(1);   // x1 -> x2
    gatherfinal_kernel<<<GB, 256>>>(out); // x2 -> out (fused final)
}

// round 16
// speedup vs baseline: 1.0990x; 1.0120x over previous
#include <cuda_runtime.h>
#include <cuda_fp16.h>
#include <math.h>
#include <stdint.h>

// ---------------- problem constants ----------------
static constexpr int NUSERS = 100000;
static constexpr int NITEMS = 50000;
static constexpr int NNODE  = 150000;       // NUSERS + NITEMS
static constexpr int NEDGE  = 1200000;      // 2 * 600000
static constexpr int DIM    = 64;
static constexpr int SCANB  = (NNODE + 1023) / 1024;     // 147 scan blocks
static constexpr int EDGE4B = (NEDGE / 4 + 255) / 256;   // mlp blocks (4 edges/thread)
static constexpr int EDGE2B = (NEDGE / 2 + 255) / 256;   // scatter blocks
static constexpr int VECB   = (NNODE * 16 + 255) / 256;  // init blocks
static constexpr int GB     = NNODE / 16;                // gather blocks (2 nodes/warp, 8 warps)

// ---------------- device scratch (static; no runtime alloc) ----------------
// Invariant: g_wdeg/g_cnt are ZERO at kernel_launch entry (static init covers
// the first call; gather layer 0 re-zeros them after scan3 has consumed them).
__device__ float  g_edge_w[NEDGE];
__device__ int    g_rank[NEDGE];            // rank of edge within its dst bucket
__device__ int2   g_edge[NEDGE];            // {src, __float_as_int(edge_w * dinv[src])}
__device__ float  g_wdeg[NNODE];
__device__ float  g_dinv[NNODE];
__device__ int    g_cnt[NNODE];
__device__ int    g_rowptr[NNODE + 1];
__device__ int    g_bsum[SCANB];
__device__ __half g_x0[(size_t)NNODE * DIM];
__device__ __half g_x1[(size_t)NNODE * DIM];
__device__ __half g_x2[(size_t)NNODE * DIM];
__device__ __half* const g_xptr[3] = {g_x0, g_x1, g_x2};

// ---------------- kernels ----------------

// edge gate MLP, 4 edges per thread: sigmoid(relu(f @ W1 + b1) @ w2 + b2).
// Each set of 8 weight LDS feeds 32 FMAs. Histogram wdeg + cnt; cnt atomic's
// return value = edge rank in dst bucket (consumed by the atomic-free scatter).
__global__ void __launch_bounds__(256) mlp_kernel(
        const float* __restrict__ ef,
        const float* __restrict__ w1,  const float* __restrict__ b1,
        const float* __restrict__ w2,  const float* __restrict__ b2,
        const int*   __restrict__ eidx) {
    __shared__ float sW1[8 * 32];
    __shared__ float sB1[32];
    __shared__ float sW2[32];
    __shared__ float sB2;
    int t = threadIdx.x;
    if (t < 256) sW1[t] = w1[t];
    if (t < 32)  { sB1[t] = b1[t]; sW2[t] = w2[t]; }
    if (t == 0)  sB2 = b2[0];
    __syncthreads();

    int e0 = (blockIdx.x * 256 + t) * 4;
    if (e0 >= NEDGE) return;               // NEDGE % 4 == 0: all 4 edges valid

    float f[4][8];
    #pragma unroll
    for (int c = 0; c < 4; c++) {
        const float4* fp = reinterpret_cast<const float4*>(ef + (size_t)(e0 + c) * 8);
        float4 fa = __ldg(fp);
        float4 fb = __ldg(fp + 1);
        f[c][0] = fa.x; f[c][1] = fa.y; f[c][2] = fa.z; f[c][3] = fa.w;
        f[c][4] = fb.x; f[c][5] = fb.y; f[c][6] = fb.z; f[c][7] = fb.w;
    }
    float out[4] = {sB2, sB2, sB2, sB2};
    #pragma unroll
    for (int j = 0; j < 32; j++) {
        float wc[8];
        #pragma unroll
        for (int i = 0; i < 8; i++) wc[i] = sW1[i * 32 + j];   // 8 LDS serve 32 FMAs
        float bj = sB1[j], w2j = sW2[j];
        #pragma unroll
        for (int c = 0; c < 4; c++) {
            float h = bj;
            #pragma unroll
            for (int i = 0; i < 8; i++) h = fmaf(f[c][i], wc[i], h);
            h = fmaxf(h, 0.f);
            out[c] = fmaf(h, w2j, out[c]);
        }
    }
    int4 c4 = __ldg(reinterpret_cast<const int4*>(eidx + NEDGE + e0));
    int cs[4] = {c4.x, c4.y, c4.z, c4.w};
    float wv[4];
    #pragma unroll
    for (int c = 0; c < 4; c++) wv[c] = 1.f / (1.f + expf(-out[c]));
    *reinterpret_cast<float4*>(g_edge_w + e0) = make_float4(wv[0], wv[1], wv[2], wv[3]);
    int rk[4];
    #pragma unroll
    for (int c = 0; c < 4; c++) {
        atomicAdd(&g_wdeg[cs[c]], wv[c]);
        rk[c] = atomicAdd(&g_cnt[cs[c]], 1);
    }
    *reinterpret_cast<int4*>(g_rank + e0) = make_int4(rk[0], rk[1], rk[2], rk[3]);
}

// warp-shuffle scan helpers
__device__ __forceinline__ int warp_incl_scan(int v, int lane) {
    #pragma unroll
    for (int k = 1; k < 32; k <<= 1) {
        int u = __shfl_up_sync(0xffffffffu, v, k);
        if (lane >= k) v += u;
    }
    return v;
}

// scan phase 1: per-block sums of g_cnt (256 thr x 4 elems = 1024 nodes/block)
__global__ void __launch_bounds__(256) scan1_kernel() {
    __shared__ int wtot[8];
    int t = threadIdx.x, lane = t & 31, w = t >> 5;
    int n0 = blockIdx.x * 1024 + t * 4;

    int s;
    if (n0 + 3 < NNODE) {
        int4 c = *reinterpret_cast<const int4*>(g_cnt + n0);
        s = c.x + c.y + c.z + c.w;
    } else {
        s = 0;
        #pragma unroll
        for (int i = 0; i < 4; i++) if (n0 + i < NNODE) s += g_cnt[n0 + i];
    }
    #pragma unroll
    for (int k = 16; k > 0; k >>= 1) s += __shfl_xor_sync(0xffffffffu, s, k);
    if (lane == 0) wtot[w] = s;
    __syncthreads();
    if (t == 0) {
        int tot = 0;
        #pragma unroll
        for (int i = 0; i < 8; i++) tot += wtot[i];
        g_bsum[blockIdx.x] = tot;
    }
}

// scan phase 2+3: redundant scan of the 147 block sums + local exclusive scan
// (256 thr x 4 elems); writes rowptr and dinv. Warp-shuffle based, 3 barriers.
__global__ void __launch_bounds__(256) scan3_kernel() {
    __shared__ int wtotA[8];
    __shared__ int bincl[256];
    __shared__ int wtotB[8];
    int t = threadIdx.x, lane = t & 31, w = t >> 5;

    // ---- redundant inclusive scan of g_bsum[0..SCANB) over 256 lanes ----
    int bv = (t < SCANB) ? g_bsum[t] : 0;
    int bs = warp_incl_scan(bv, lane);
    if (lane == 31) wtotA[w] = bs;
    __syncthreads();
    int offA = 0;
    #pragma unroll
    for (int i = 0; i < 8; i++) offA += (i < w) ? wtotA[i] : 0;
    bincl[t] = bs + offA;
    __syncthreads();
    int blockOff = (blockIdx.x == 0) ? 0 : bincl[blockIdx.x - 1];

    // ---- local exclusive scan of this block's 1024 cnt values ----
    int n0 = blockIdx.x * 1024 + t * 4;
    int c0 = 0, c1 = 0, c2 = 0, c3 = 0;
    if (n0 + 3 < NNODE) {
        int4 c = *reinterpret_cast<const int4*>(g_cnt + n0);
        c0 = c.x; c1 = c.y; c2 = c.z; c3 = c.w;
    } else {
        if (n0     < NNODE) c0 = g_cnt[n0];
        if (n0 + 1 < NNODE) c1 = g_cnt[n0 + 1];
        if (n0 + 2 < NNODE) c2 = g_cnt[n0 + 2];
        if (n0 + 3 < NNODE) c3 = g_cnt[n0 + 3];
    }
    int local = c0 + c1 + c2 + c3;
    int sinc = warp_incl_scan(local, lane);
    if (lane == 31) wtotB[w] = sinc;
    __syncthreads();
    int offB = 0;
    #pragma unroll
    for (int i = 0; i < 8; i++) offB += (i < w) ? wtotB[i] : 0;
    int p = blockOff + offB + sinc - local;   // global exclusive prefix at n0

    int r0 = p, r1 = p + c0, r2 = r1 + c1, r3 = r2 + c2;
    if (n0 + 3 < NNODE) {
        *reinterpret_cast<int4*>(g_rowptr + n0) = make_int4(r0, r1, r2, r3);
        float4 dg = *reinterpret_cast<const float4*>(g_wdeg + n0);
        float4 dv;
        dv.x = (dg.x > 0.f) ? rsqrtf(dg.x) : 0.f;
        dv.y = (dg.y > 0.f) ? rsqrtf(dg.y) : 0.f;
        dv.z = (dg.z > 0.f) ? rsqrtf(dg.z) : 0.f;
        dv.w = (dg.w > 0.f) ? rsqrtf(dg.w) : 0.f;
        *reinterpret_cast<float4*>(g_dinv + n0) = dv;
    } else {
        int rr[4] = {r0, r1, r2, r3};
        #pragma unroll
        for (int i = 0; i < 4; i++) {
            if (n0 + i < NNODE) {
                g_rowptr[n0 + i] = rr[i];
                float dg = g_wdeg[n0 + i];
                g_dinv[n0 + i] = (dg > 0.f) ? rsqrtf(dg) : 0.f;
            }
        }
    }
    if (blockIdx.x == 0 && t == 0) g_rowptr[NNODE] = NEDGE;
}

// fused scatter + init (ATOMIC-FREE scatter: position = rowptr[dst] + rank):
//   blocks [0, EDGE2B): place edges {src, edge_w*dinv[src]} at their slot
//   blocks [EDGE2B, EDGE2B+VECB): x0 = l2norm(...) node init
__global__ void __launch_bounds__(256) scatterinit_kernel(
        const int*   __restrict__ eidx,
        const float* __restrict__ uemb,  const float* __restrict__ audio,
        const float* __restrict__ art,   const float* __restrict__ alb,
        const int*   __restrict__ aid,   const int*   __restrict__ bid) {
    if (blockIdx.x < EDGE2B) {
        int e = (blockIdx.x * 256 + threadIdx.x) * 2;
        if (e >= NEDGE) return;
        int2   r2 = __ldg(reinterpret_cast<const int2*>(eidx + e));
        int2   c2 = __ldg(reinterpret_cast<const int2*>(eidx + NEDGE + e));
        float2 w2 = __ldg(reinterpret_cast<const float2*>(g_edge_w + e));
        int2   k2 = __ldg(reinterpret_cast<const int2*>(g_rank + e));

        float wa = w2.x * __ldg(&g_dinv[r2.x]);
        g_edge[__ldg(&g_rowptr[c2.x]) + k2.x] = make_int2(r2.x, __float_as_int(wa));

        float wb = w2.y * __ldg(&g_dinv[r2.y]);
        g_edge[__ldg(&g_rowptr[c2.y]) + k2.y] = make_int2(r2.y, __float_as_int(wb));
    } else {
        int t = (blockIdx.x - EDGE2B) * 256 + threadIdx.x;
        int node = t >> 4;
        int sub  = t & 15;
        if (node >= NNODE) return;

        float4 v;
        if (node < NUSERS) {
            v = __ldg(reinterpret_cast<const float4*>(uemb) + (size_t)node * 16 + sub);
        } else {
            int i = node - NUSERS;
            int a = __ldg(&aid[i]);
            int b = __ldg(&bid[i]);
            float4 pa = __ldg(reinterpret_cast<const float4*>(audio) + (size_t)i * 16 + sub);
            float4 pr = __ldg(reinterpret_cast<const float4*>(art)   + (size_t)a * 16 + sub);
            float4 pl = __ldg(reinterpret_cast<const float4*>(alb)   + (size_t)b * 16 + sub);
            v.x = pa.x * 0.3f + (pr.x + pl.x) * 0.44f;
            v.y = pa.y * 0.3f + (pr.y + pl.y) * 0.44f;
            v.z = pa.z * 0.3f + (pr.z + pl.z) * 0.44f;
            v.w = pa.w * 0.3f + (pr.w + pl.w) * 0.44f;
        }
        float ss = v.x * v.x + v.y * v.y + v.z * v.z + v.w * v.w;
        #pragma unroll
        for (int o = 8; o > 0; o >>= 1) ss += __shfl_xor_sync(0xffffffffu, ss, o);
        float inv = 1.f / fmaxf(sqrtf(ss), 1e-12f);

        __half2 h0 = __floats2half2_rn(v.x * inv, v.y * inv);
        __half2 h1 = __floats2half2_rn(v.z * inv, v.w * inv);
        uint2 hv;
        hv.x = *reinterpret_cast<unsigned int*>(&h0);
        hv.y = *reinterpret_cast<unsigned int*>(&h1);
        reinterpret_cast<uint2*>(g_x0)[(size_t)node * 16 + sub] = hv;
    }
}

// ---- gather segment: lane owns dims {2*lane, 2*lane+1} of the dst node ----
// Edge meta for up to 32 edges staged in ONE coalesced int2 load; each edge is
// ONE warp-wide 128B row load (4B/lane). 8 independent loads in flight per
// group; padded edges contribute w=0 (src=0 is a valid, safe row).
__device__ __forceinline__ float2 gather_seg(const unsigned* __restrict__ xin,
                                             int beg, int end, int lane) {
    float a0 = 0.f, a1 = 0.f;
    for (int base = beg; base < end; base += 32) {
        int idx = base + lane;
        int2 m = (idx < end) ? __ldg(&g_edge[idx]) : make_int2(0, 0);
        int nr = (min(end - base, 32) + 7) & ~7;   // round up to group of 8
        for (int g = 0; g < nr; g += 8) {
            unsigned v[8];
            float    w[8];
            #pragma unroll
            for (int k = 0; k < 8; k++) {
                int src = __shfl_sync(0xffffffffu, m.x, g + k);
                w[k] = __int_as_float(__shfl_sync(0xffffffffu, m.y, g + k));
                v[k] = __ldg(xin + (size_t)src * 32 + lane);
            }
            #pragma unroll
            for (int k = 0; k < 8; k++) {
                float2 f = __half22float2(*reinterpret_cast<__half2*>(&v[k]));
                a0 = fmaf(w[k], f.x, a0);
                a1 = fmaf(w[k], f.y, a1);
            }
        }
    }
    return make_float2(a0, a1);
}

// layers 0,1: x[l+1][n] = dinv[n] * sum.  Warp = 2 consecutive nodes (adjacent
// CSR segments); shared prologue. Layer 0 also re-zeros wdeg/cnt (post-scan).
__global__ void __launch_bounds__(256) gather_kernel(int layer) {
    const unsigned* __restrict__ xin  = reinterpret_cast<const unsigned*>(g_xptr[layer]);
    unsigned*       __restrict__ xout = reinterpret_cast<unsigned*>(g_xptr[layer + 1]);

    int gt = blockIdx.x * blockDim.x + threadIdx.x;
    if (layer == 0 && gt < NNODE) { g_wdeg[gt] = 0.f; g_cnt[gt] = 0; }

    int lane = threadIdx.x & 31;
    int n0 = (gt >> 5) * 2;                       // 2 nodes per warp

    int rp = __ldg(&g_rowptr[n0 + min(lane, 2)]);
    int beg = __shfl_sync(0xffffffffu, rp, 0);
    int mid = __shfl_sync(0xffffffffu, rp, 1);
    int end = __shfl_sync(0xffffffffu, rp, 2);
    float dvl = __ldg(&g_dinv[n0 + (lane & 1)]);
    float dv0 = __shfl_sync(0xffffffffu, dvl, 0);
    float dv1 = __shfl_sync(0xffffffffu, dvl, 1);

    float2 a = gather_seg(xin, beg, mid, lane);
    __half2 h0 = __floats2half2_rn(a.x * dv0, a.y * dv0);
    xout[(size_t)n0 * 32 + lane] = *reinterpret_cast<unsigned*>(&h0);

    float2 b = gather_seg(xin, mid, end, lane);
    __half2 h1 = __floats2half2_rn(b.x * dv1, b.y * dv1);
    xout[(size_t)(n0 + 1) * 32 + lane] = *reinterpret_cast<unsigned*>(&h1);
}

// layer 2 fused with final: out = l2norm((x0+x1+x2+x3)/4), x3 kept fp32.
__global__ void __launch_bounds__(256) gatherfinal_kernel(float* __restrict__ out) {
    int gt = blockIdx.x * blockDim.x + threadIdx.x;
    if (gt == 0) out[(size_t)NNODE * DIM] = 0.f;   // align_loss scalar

    int lane = threadIdx.x & 31;
    int n0 = (gt >> 5) * 2;

    int rp = __ldg(&g_rowptr[n0 + min(lane, 2)]);
    int beg = __shfl_sync(0xffffffffu, rp, 0);
    int mid = __shfl_sync(0xffffffffu, rp, 1);
    int end = __shfl_sync(0xffffffffu, rp, 2);
    float dvl = __ldg(&g_dinv[n0 + (lane & 1)]);
    float dv0 = __shfl_sync(0xffffffffu, dvl, 0);
    float dv1 = __shfl_sync(0xffffffffu, dvl, 1);

    const unsigned* x2p = reinterpret_cast<const unsigned*>(g_x2);
    float2 a = gather_seg(x2p, beg, mid, lane);
    float2 b = gather_seg(x2p, mid, end, lane);

    float s0 = a.x * dv0, s1 = a.y * dv0;   // node n0
    float t0 = b.x * dv1, t1 = b.y * dv1;   // node n0+1

    #pragma unroll
    for (int l = 0; l < 3; l++) {
        const unsigned* xp = reinterpret_cast<const unsigned*>(g_xptr[l]);
        unsigned va = __ldg(xp + (size_t)n0 * 32 + lane);
        unsigned vb = __ldg(xp + (size_t)(n0 + 1) * 32 + lane);
        float2 fa = __half22float2(*reinterpret_cast<__half2*>(&va));
        float2 fb = __half22float2(*reinterpret_cast<__half2*>(&vb));
        s0 += fa.x; s1 += fa.y;
        t0 += fb.x; t1 += fb.y;
    }
    s0 *= 0.25f; s1 *= 0.25f; t0 *= 0.25f; t1 *= 0.25f;
    float ssA = fmaf(s0, s0, s1 * s1);
    float ssB = fmaf(t0, t0, t1 * t1);
    #pragma unroll
    for (int o = 16; o > 0; o >>= 1) {
        ssA += __shfl_xor_sync(0xffffffffu, ssA, o);
        ssB += __shfl_xor_sync(0xffffffffu, ssB, o);
    }
    float invA = 1.f / fmaxf(sqrtf(ssA), 1e-12f);
    float invB = 1.f / fmaxf(sqrtf(ssB), 1e-12f);

    float2* op = reinterpret_cast<float2*>(out);
    op[(size_t)n0 * 32 + lane]       = make_float2(s0 * invA, s1 * invA);
    op[(size_t)(n0 + 1) * 32 + lane] = make_float2(t0 * invB, t1 * invB);
}

// ---------------- launcher ----------------
extern "C" void kernel_launch(void* const* d_in, const int* in_sizes, int n_in,
                              void* d_out, int out_size) {
    const float* uemb  = (const float*)d_in[0];
    const float* audio = (const float*)d_in[1];
    const float* art   = (const float*)d_in[2];
    const float* alb   = (const float*)d_in[3];
    const float* w1    = (const float*)d_in[4];
    const float* b1    = (const float*)d_in[5];
    const float* w2    = (const float*)d_in[6];
    const float* b2    = (const float*)d_in[7];
    const float* ef    = (const float*)d_in[8];
    const int*   eidx  = (const int*)  d_in[9];
    const int*   aid   = (const int*)  d_in[10];
    const int*   bid   = (const int*)  d_in[11];
    float* out = (float*)d_out;

    mlp_kernel        <<<EDGE4B, 256>>>(ef, w1, b1, w2, b2, eidx);
    scan1_kernel      <<<SCANB, 256>>>();
    scan3_kernel      <<<SCANB, 256>>>();
    scatterinit_kernel<<<EDGE2B + VECB, 256>>>(eidx, uemb, audio, art, alb, aid, bid);
    gather_kernel     <<<GB, 256>>>(0);   // x0 -> x1  (also re-zeros wdeg/cnt)
    gather_kernel     <<<GB, 256>>>(1);   // x1 -> x2
    gatherfinal_kernel<<<GB, 256>>>(out); // x2 -> out (fused final)
}